// round 11
// baseline (speedup 1.0000x reference)
#include <cuda_runtime.h>
#include <cuda_bf16.h>
#include <cuda_fp16.h>
#include <mma.h>
#include <stdint.h>

using namespace nvcuda;

#define N_NODES 10000
#define D 256
#define ROW_WORDS 320   // ceil(10000/32)=313, padded to 320 (1280 B/row)

// ---------------- scratch (device globals; no allocation allowed) ----------
__device__ __align__(16) unsigned int g_bitmap[N_NODES * ROW_WORDS];  // 12.8 MB
__device__ float g_dinv[N_NODES];
__device__ __align__(16) __half g_zs_h[N_NODES * D];     // fp16 dinv[j]*(x@W)[j,:]
__device__ __align__(16) __nv_bfloat16 g_wh[D * D];      // W hi  [k][n]
__device__ __align__(16) __nv_bfloat16 g_wl[D * D];      // W lo  [k][n]
__device__ __align__(16) __nv_bfloat16 g_xh[N_NODES * D];  // x hi  [m][k]
__device__ __align__(16) __nv_bfloat16 g_xl[N_NODES * D];  // x lo  [m][k]
__device__ int g_mode;   // 0 = int32 edge layout, 1 = raw int64 layout

// ---------------------------------------------------------------------------
__device__ __forceinline__ unsigned long long split4(float4 v, unsigned long long& lo) {
    unsigned short h0 = __bfloat16_as_ushort(__float2bfloat16(v.x));
    unsigned short h1 = __bfloat16_as_ushort(__float2bfloat16(v.y));
    unsigned short h2 = __bfloat16_as_ushort(__float2bfloat16(v.z));
    unsigned short h3 = __bfloat16_as_ushort(__float2bfloat16(v.w));
    float f0 = __uint_as_float((unsigned)h0 << 16);
    float f1 = __uint_as_float((unsigned)h1 << 16);
    float f2 = __uint_as_float((unsigned)h2 << 16);
    float f3 = __uint_as_float((unsigned)h3 << 16);
    unsigned short l0 = __bfloat16_as_ushort(__float2bfloat16(v.x - f0));
    unsigned short l1 = __bfloat16_as_ushort(__float2bfloat16(v.y - f1));
    unsigned short l2 = __bfloat16_as_ushort(__float2bfloat16(v.z - f2));
    unsigned short l3 = __bfloat16_as_ushort(__float2bfloat16(v.w - f3));
    lo = (unsigned long long)l0 | ((unsigned long long)l1 << 16)
       | ((unsigned long long)l2 << 32) | ((unsigned long long)l3 << 48);
    return (unsigned long long)h0 | ((unsigned long long)h1 << 16)
         | ((unsigned long long)h2 << 32) | ((unsigned long long)h3 << 48);
}

// Split x and W into bf16 hi/lo (one float4 of x per thread; first threads do W)
__global__ void prep_kernel(const float* __restrict__ x, const float* __restrict__ w) {
    int idx = blockIdx.x * blockDim.x + threadIdx.x;
    const int NX4 = N_NODES * D / 4;   // 640000
    if (idx < NX4) {
        unsigned long long lo;
        unsigned long long hi = split4(((const float4*)x)[idx], lo);
        *(unsigned long long*)&g_xh[idx * 4] = hi;
        *(unsigned long long*)&g_xl[idx * 4] = lo;
    }
    if (idx < D * D / 4) {             // 16384
        unsigned long long lo;
        unsigned long long hi = split4(((const float4*)w)[idx], lo);
        *(unsigned long long*)&g_wh[idx * 4] = hi;
        *(unsigned long long*)&g_wl[idx * 4] = lo;
    }
}

// Zero bitmap (all blocks) + edge-layout detection (block 0)
__global__ void zero_detect_kernel(const int* __restrict__ ei, int n_words) {
    int idx = blockIdx.x * blockDim.x + threadIdx.x;
    const int total = N_NODES * ROW_WORDS / 4;
    uint4 z = make_uint4(0u, 0u, 0u, 0u);
    for (int i = idx; i < total; i += gridDim.x * blockDim.x)
        ((uint4*)g_bitmap)[i] = z;

    if (blockIdx.x == 0) {
        __shared__ unsigned int s_or[8];
        int t = threadIdx.x;           // 256 threads, check 512 odd words
        unsigned int v = 0;
        int i0 = 4 * t + 1, i1 = 4 * t + 3;
        if (i0 < n_words) v |= (unsigned int)ei[i0];
        if (i1 < n_words) v |= (unsigned int)ei[i1];
        #pragma unroll
        for (int o = 16; o > 0; o >>= 1) v |= __shfl_down_sync(0xffffffffu, v, o);
        if ((t & 31) == 0) s_or[t >> 5] = v;
        __syncthreads();
        if (t == 0) {
            unsigned int r = 0;
            #pragma unroll
            for (int w2 = 0; w2 < 8; w2++) r |= s_or[w2];
            g_mode = (r == 0u) ? 1 : 0;   // all-zero odd words => int64
        }
    }
}

// 2 edges per thread, vector loads
__global__ void set_edges_kernel(const int* __restrict__ ei, int E) {
    int t = blockIdx.x * blockDim.x + threadIdx.x;
    int base = t * 2;
    if (base >= E) return;
    int s[2], d[2];
    bool vec = ((E & 1) == 0) && (base + 1 < E);
    if (g_mode) {
        if (vec) {
            int4 a = ((const int4*)ei)[t];
            int4 b = ((const int4*)(ei + 2 * E))[t];
            s[0] = a.x; s[1] = a.z;
            d[0] = b.x; d[1] = b.z;
        } else {
            #pragma unroll
            for (int q = 0; q < 2; q++) {
                int e = base + q;
                s[q] = (e < E) ? ei[2 * e] : -1;
                d[q] = (e < E) ? ei[2 * E + 2 * e] : -1;
            }
        }
    } else {
        if (vec) {
            int2 a = ((const int2*)ei)[t];
            int2 b = ((const int2*)(ei + E))[t];
            s[0] = a.x; s[1] = a.y;
            d[0] = b.x; d[1] = b.y;
        } else {
            #pragma unroll
            for (int q = 0; q < 2; q++) {
                int e = base + q;
                s[q] = (e < E) ? ei[e] : -1;
                d[q] = (e < E) ? ei[E + e] : -1;
            }
        }
    }
    #pragma unroll
    for (int q = 0; q < 2; q++) {
        if ((unsigned)s[q] < N_NODES && (unsigned)d[q] < N_NODES) {
            atomicOr(&g_bitmap[s[q] * ROW_WORDS + (d[q] >> 5)], 1u << (d[q] & 31));
            atomicOr(&g_bitmap[d[q] * ROW_WORDS + (s[q] >> 5)], 1u << (s[q] & 31));
        }
    }
}

// One warp per row, uint4 loads for MLP: deg = popcount(row) + 1
__global__ void dinv_kernel() {
    int warp = (blockIdx.x * blockDim.x + threadIdx.x) >> 5;
    int lane = threadIdx.x & 31;
    if (warp >= N_NODES) return;
    const uint4* row = (const uint4*)&g_bitmap[warp * ROW_WORDS];  // 80 uint4
    int cnt = 0;
    #pragma unroll
    for (int t = 0; t < 3; t++) {
        int idx = lane + t * 32;
        if (idx < 80) {
            uint4 v = row[idx];
            cnt += __popc(v.x) + __popc(v.y) + __popc(v.z) + __popc(v.w);
        }
    }
    #pragma unroll
    for (int o = 16; o > 0; o >>= 1)
        cnt += __shfl_down_sync(0xffffffffu, cnt, o);
    if (lane == 0) g_dinv[warp] = rsqrtf((float)(cnt + 1));
}

// ---------------------------------------------------------------------------
// wmma bf16 GEMM (3-term split, double-buffered): zs = dinv .* (x @ W)  (fp16 out)
// CTA tile 128(M) x 128(N), BK=32, 8 warps (2 M x 4 N), warp tile 64x32.
#define LDA 40    // 128 x 40 bf16 (80 B/row)
#define LDB 136   // 32 x 136 bf16 (272 B/row)
#define LDC 132   // 128 x 132 f32 (528 B/row)
#define SM_AH 0
#define SM_AL 10240
#define SM_BH 20480
#define SM_BL 29184
#define BUF_BYTES 37888
#define SMEM_GEMM (2 * BUF_BYTES)   // 75776; epilogue C (67584) reuses from 0

__global__ __launch_bounds__(256) void gemm_wmma_kernel() {
    extern __shared__ char smem[];
    float* sC = (float*)smem;

    int tid = threadIdx.x;
    int wid = tid >> 5;
    int warp_m = wid & 1;        // 0..1  (64 rows)
    int warp_n = wid >> 1;       // 0..3  (32 cols)
    int bm = blockIdx.x * 128;
    int bn = blockIdx.y * 128;

    // per-thread load coords
    int a_row = tid >> 1;                 // 0..127 (2 uint4-slots per row? no:)
    // A tile per chunk: 128 rows x 32 bf16 = 512 uint4 (hi), 512 (lo); 2 each/thread
    // thread t handles uint4 index lin = t and t+256 -> row = lin>>2, q = lin&3
    // B tile per chunk: 32 rows x 128 bf16 = 512 uint4 each; same split
    (void)a_row;

    wmma::fragment<wmma::accumulator, 16, 16, 16, float> acc[4][2];
    #pragma unroll
    for (int mi = 0; mi < 4; mi++)
        #pragma unroll
        for (int ni = 0; ni < 2; ni++)
            wmma::fill_fragment(acc[mi][ni], 0.0f);

    uint4 pAh[2], pAl[2], pBh[2], pBl[2];

    // ---- prologue: load chunk 0 into regs
    #pragma unroll
    for (int t = 0; t < 2; t++) {
        int lin = tid + t * 256;
        int row = lin >> 2, q = lin & 3;
        int m = bm + row;
        if (m < N_NODES) {
            pAh[t] = *(const uint4*)&g_xh[(size_t)m * D + q * 8];
            pAl[t] = *(const uint4*)&g_xl[(size_t)m * D + q * 8];
        } else {
            pAh[t] = make_uint4(0, 0, 0, 0);
            pAl[t] = make_uint4(0, 0, 0, 0);
        }
        int kr = lin >> 4, nq = lin & 15;
        int gi = kr * D + bn + nq * 8;
        pBh[t] = *(const uint4*)&g_wh[gi];
        pBl[t] = *(const uint4*)&g_wl[gi];
    }
    {
        char* buf = smem;
        __nv_bfloat16* sAh = (__nv_bfloat16*)(buf + SM_AH);
        __nv_bfloat16* sAl = (__nv_bfloat16*)(buf + SM_AL);
        __nv_bfloat16* sBh = (__nv_bfloat16*)(buf + SM_BH);
        __nv_bfloat16* sBl = (__nv_bfloat16*)(buf + SM_BL);
        #pragma unroll
        for (int t = 0; t < 2; t++) {
            int lin = tid + t * 256;
            int row = lin >> 2, q = lin & 3;
            *(uint4*)&sAh[row * LDA + q * 8] = pAh[t];
            *(uint4*)&sAl[row * LDA + q * 8] = pAl[t];
            int kr = lin >> 4, nq = lin & 15;
            *(uint4*)&sBh[kr * LDB + nq * 8] = pBh[t];
            *(uint4*)&sBl[kr * LDB + nq * 8] = pBl[t];
        }
    }
    __syncthreads();

    for (int kc = 0; kc < 8; kc++) {
        // prefetch next chunk to regs
        if (kc < 7) {
            int k0 = (kc + 1) * 32;
            #pragma unroll
            for (int t = 0; t < 2; t++) {
                int lin = tid + t * 256;
                int row = lin >> 2, q = lin & 3;
                int m = bm + row;
                if (m < N_NODES) {
                    pAh[t] = *(const uint4*)&g_xh[(size_t)m * D + k0 + q * 8];
                    pAl[t] = *(const uint4*)&g_xl[(size_t)m * D + k0 + q * 8];
                } else {
                    pAh[t] = make_uint4(0, 0, 0, 0);
                    pAl[t] = make_uint4(0, 0, 0, 0);
                }
                int kr = lin >> 4, nq = lin & 15;
                int gi = (k0 + kr) * D + bn + nq * 8;
                pBh[t] = *(const uint4*)&g_wh[gi];
                pBl[t] = *(const uint4*)&g_wl[gi];
            }
        }

        // mma on current buffer
        {
            char* buf = smem + (kc & 1) * BUF_BYTES;
            __nv_bfloat16* sAh = (__nv_bfloat16*)(buf + SM_AH);
            __nv_bfloat16* sAl = (__nv_bfloat16*)(buf + SM_AL);
            __nv_bfloat16* sBh = (__nv_bfloat16*)(buf + SM_BH);
            __nv_bfloat16* sBl = (__nv_bfloat16*)(buf + SM_BL);
            #pragma unroll
            for (int kk = 0; kk < 32; kk += 16) {
                wmma::fragment<wmma::matrix_b, 16, 16, 16, __nv_bfloat16, wmma::row_major> bh[2], bl[2];
                #pragma unroll
                for (int ni = 0; ni < 2; ni++) {
                    wmma::load_matrix_sync(bh[ni], &sBh[kk * LDB + warp_n * 32 + ni * 16], LDB);
                    wmma::load_matrix_sync(bl[ni], &sBl[kk * LDB + warp_n * 32 + ni * 16], LDB);
                }
                #pragma unroll
                for (int mi = 0; mi < 4; mi++) {
                    wmma::fragment<wmma::matrix_a, 16, 16, 16, __nv_bfloat16, wmma::row_major> ah, al;
                    wmma::load_matrix_sync(ah, &sAh[(warp_m * 64 + mi * 16) * LDA + kk], LDA);
                    wmma::load_matrix_sync(al, &sAl[(warp_m * 64 + mi * 16) * LDA + kk], LDA);
                    #pragma unroll
                    for (int ni = 0; ni < 2; ni++) {
                        wmma::mma_sync(acc[mi][ni], ah, bh[ni], acc[mi][ni]);
                        wmma::mma_sync(acc[mi][ni], ah, bl[ni], acc[mi][ni]);
                        wmma::mma_sync(acc[mi][ni], al, bh[ni], acc[mi][ni]);
                    }
                }
            }
        }

        // store prefetched chunk to other buffer
        if (kc < 7) {
            char* buf = smem + ((kc + 1) & 1) * BUF_BYTES;
            __nv_bfloat16* sAh = (__nv_bfloat16*)(buf + SM_AH);
            __nv_bfloat16* sAl = (__nv_bfloat16*)(buf + SM_AL);
            __nv_bfloat16* sBh = (__nv_bfloat16*)(buf + SM_BH);
            __nv_bfloat16* sBl = (__nv_bfloat16*)(buf + SM_BL);
            #pragma unroll
            for (int t = 0; t < 2; t++) {
                int lin = tid + t * 256;
                int row = lin >> 2, q = lin & 3;
                *(uint4*)&sAh[row * LDA + q * 8] = pAh[t];
                *(uint4*)&sAl[row * LDA + q * 8] = pAl[t];
                int kr = lin >> 4, nq = lin & 15;
                *(uint4*)&sBh[kr * LDB + nq * 8] = pBh[t];
                *(uint4*)&sBl[kr * LDB + nq * 8] = pBl[t];
            }
            __syncthreads();
        }
    }
    __syncthreads();   // all mma reads done before sC overwrites smem

    // Epilogue: frags -> smem -> scale by dinv -> g_zs_h (fp16)
    #pragma unroll
    for (int mi = 0; mi < 4; mi++)
        #pragma unroll
        for (int ni = 0; ni < 2; ni++)
            wmma::store_matrix_sync(
                &sC[(warp_m * 64 + mi * 16) * LDC + warp_n * 32 + ni * 16],
                acc[mi][ni], LDC, wmma::mem_row_major);
    __syncthreads();

    #pragma unroll
    for (int t = 0; t < 16; t++) {
        int lin = tid + t * 256;
        int row = lin >> 5, c4 = lin & 31;
        int m = bm + row;
        if (m < N_NODES) {
            float dv = g_dinv[m];
            float4 v = *(float4*)&sC[row * LDC + c4 * 4];
            __half2 h01 = __floats2half2_rn(v.x * dv, v.y * dv);
            __half2 h23 = __floats2half2_rn(v.z * dv, v.w * dv);
            uint2 o;
            o.x = *(unsigned int*)&h01;
            o.y = *(unsigned int*)&h23;
            *(uint2*)&g_zs_h[(size_t)m * D + bn + c4 * 4] = o;
        }
    }
}

// ---------------------------------------------------------------------------
// SpMM over the bitmap: out[i,:] = dinv[i] * (sum_{bit(i,j)} zs[j,:] + zs[i,:])
#define SCHUNK 128
#define SCAP (SCHUNK * 32)

__global__ __launch_bounds__(128) void spmm_kernel(float* __restrict__ out) {
    __shared__ int s_idx[SCAP];
    __shared__ int s_cnt;
    int i = blockIdx.x;
    int t = threadIdx.x;                         // dim pair t -> dims 2t, 2t+1
    const unsigned int* row = &g_bitmap[i * ROW_WORDS];
    const __half2* zs2 = (const __half2*)g_zs_h;

    float2 a0 = {0.f, 0.f}, a1 = {0.f, 0.f}, a2 = {0.f, 0.f}, a3 = {0.f, 0.f};

    for (int cw = 0; cw < ROW_WORDS; cw += SCHUNK) {
        if (t == 0) s_cnt = 0;
        __syncthreads();
        int w = cw + t;
        unsigned int bits = (w < ROW_WORDS) ? row[w] : 0u;
        while (bits) {
            int b = __ffs(bits) - 1;
            bits &= bits - 1;
            s_idx[atomicAdd(&s_cnt, 1)] = (w << 5) + b;
        }
        __syncthreads();
        int nb = s_cnt;
        int k = 0;
        for (; k + 4 <= nb; k += 4) {
            int j0 = s_idx[k + 0];
            int j1 = s_idx[k + 1];
            int j2 = s_idx[k + 2];
            int j3 = s_idx[k + 3];
            float2 v0 = __half22float2(zs2[(size_t)j0 * 128 + t]);
            float2 v1 = __half22float2(zs2[(size_t)j1 * 128 + t]);
            float2 v2 = __half22float2(zs2[(size_t)j2 * 128 + t]);
            float2 v3 = __half22float2(zs2[(size_t)j3 * 128 + t]);
            a0.x += v0.x; a0.y += v0.y;
            a1.x += v1.x; a1.y += v1.y;
            a2.x += v2.x; a2.y += v2.y;
            a3.x += v3.x; a3.y += v3.y;
        }
        for (; k < nb; k++) {
            float2 v = __half22float2(zs2[(size_t)s_idx[k] * 128 + t]);
            a0.x += v.x; a0.y += v.y;
        }
        __syncthreads();
    }

    float2 self = __half22float2(zs2[(size_t)i * 128 + t]);
    float dv = g_dinv[i];
    float2 r;
    r.x = dv * ((a0.x + a1.x) + (a2.x + a3.x) + self.x);
    r.y = dv * ((a0.y + a1.y) + (a2.y + a3.y) + self.y);
    ((float2*)out)[(size_t)i * 128 + t] = r;
}

// ---------------------------------------------------------------------------
extern "C" void kernel_launch(void* const* d_in, const int* in_sizes, int n_in,
                              void* d_out, int out_size) {
    const float* x = (const float*)d_in[0];
    const int* ei = (const int*)d_in[1];
    const float* w = (const float*)d_in[2];
    float* out = (float*)d_out;
    int E = in_sizes[1] / 2;

    cudaFuncSetAttribute(gemm_wmma_kernel,
                         cudaFuncAttributeMaxDynamicSharedMemorySize, SMEM_GEMM);

    prep_kernel<<<(N_NODES * D / 4 + 255) / 256, 256>>>(x, w);
    zero_detect_kernel<<<1024, 256>>>(ei, 2 * E);
    set_edges_kernel<<<(E / 2 + 255) / 256, 256>>>(ei, E);
    dinv_kernel<<<(N_NODES * 32 + 255) / 256, 256>>>();

    dim3 ggrid((N_NODES + 127) / 128, D / 128);
    gemm_wmma_kernel<<<ggrid, 256, SMEM_GEMM>>>();

    spmm_kernel<<<N_NODES, 128>>>(out);
}